// round 10
// baseline (speedup 1.0000x reference)
#include <cuda_runtime.h>
#include <cuda_bf16.h>
#include <math.h>

#define B_    64
#define S_    256
#define BS    16384
#define M_    64
#define QD_   128
#define QAD_  256
#define VD_   128
#define FD_   128

typedef unsigned long long ull;

// ---------------- scratch ----------------
__device__ float g_w[BS * M_];
__device__ float g_e[BS * VD_];
__device__ float g_a[BS * VD_];
__device__ float g_reads[BS * VD_];
__device__ float g_partial[2 * 128];
__device__ float g_ewT[QAD_ * VD_];    // [256][128]
__device__ float g_awT[QAD_ * VD_];    // [256][128]
__device__ float g_rwT[256 * FD_];     // [256][128]
__device__ float g_keyT[QD_ * M_];     // [128][64]

// ---------------- helpers ----------------
__device__ __forceinline__ ull dup2(float x) {
    ull r; unsigned xi = __float_as_uint(x);
    asm("mov.b64 %0, {%1, %1};" : "=l"(r) : "r"(xi));
    return r;
}
__device__ __forceinline__ ull pack2(float lo, float hi) {
    ull r; unsigned a = __float_as_uint(lo), b = __float_as_uint(hi);
    asm("mov.b64 %0, {%1, %2};" : "=l"(r) : "r"(a), "r"(b));
    return r;
}
__device__ __forceinline__ void unpack2(ull v, float& lo, float& hi) {
    unsigned a, b;
    asm("mov.b64 {%0, %1}, %2;" : "=r"(a), "=r"(b) : "l"(v));
    lo = __uint_as_float(a); hi = __uint_as_float(b);
}
__device__ __forceinline__ void fma2(ull& d, ull a, ull b) {
    asm("fma.rn.f32x2 %0, %1, %2, %0;" : "+l"(d) : "l"(a), "l"(b));
}
__device__ __forceinline__ void cp16(unsigned s, const float* g) {
    asm volatile("cp.async.cg.shared.global [%0], [%1], 16;" :: "r"(s), "l"(g));
}
#define CP_COMMIT() asm volatile("cp.async.commit_group;")
#define CP_WAIT0()  asm volatile("cp.async.wait_group 0;" ::: "memory")

// ============================================================================
// K0: transpose weights into k-major scratch
// ============================================================================
__global__ void transpose_kernel(const float* __restrict__ ew,
                                 const float* __restrict__ aw,
                                 const float* __restrict__ rw,
                                 const float* __restrict__ key) {
    int t = blockIdx.x * 256 + threadIdx.x;
    int which = blockIdx.y;
    if (which < 3) {
        int k = t >> 7, n = t & 127;
        const float* src = which == 0 ? ew : (which == 1 ? aw : rw);
        float* dst = which == 0 ? g_ewT : (which == 1 ? g_awT : g_rwT);
        dst[k * 128 + n] = src[n * 256 + k];
    } else {
        if (t < QD_ * M_) {
            int k = t >> 6, n = t & 63;
            g_keyT[k * 64 + n] = key[n * 128 + k];
        }
    }
}

// ============================================================================
// K1: w = softmax(q_emb @ mem_key^T)
// ============================================================================
__global__ __launch_bounds__(256, 2) void w_kernel(const int* __restrict__ q_data,
                                                   const float* __restrict__ q_w) {
    __shared__ union {
        struct {
            __align__(16) float As[2][16][132];
            __align__(16) float Bs[2][16][68];
        } g;
        float logits[128][65];
    } sm;
    __shared__ int idx_sh[128];

    int tid = threadIdx.x;
    int r0  = blockIdx.x * 128;
    if (tid < 128) idx_sh[tid] = q_data[r0 + tid];
    __syncthreads();

    int tx = tid & 15, ty = tid >> 4;
    int rowL = tid >> 2;
    int kq   = (tid & 3) * 4;

    int bkk = tid >> 4, bcc = (tid & 15) * 4;
    unsigned bs_base = (unsigned)__cvta_generic_to_shared(&sm.g.Bs[0][0][0]);
    unsigned bs_off  = (unsigned)((bkk * 68 + bcc) * 4);
    const unsigned BS_BUF = 16 * 68 * 4;

    ull acc[8][2];
#pragma unroll
    for (int i = 0; i < 8; i++) { acc[i][0] = 0ull; acc[i][1] = 0ull; }

    float4 pa0, pa1;
    pa0 = *(const float4*)(q_w + (long)idx_sh[rowL] * QD_ + kq);
    pa1 = *(const float4*)(q_w + (long)idx_sh[rowL + 64] * QD_ + kq);
    cp16(bs_base + bs_off, g_keyT + bkk * 64 + bcc);
    CP_COMMIT();
    {
        float* a = &sm.g.As[0][kq][0];
        a[0*132+rowL]=pa0.x; a[1*132+rowL]=pa0.y; a[2*132+rowL]=pa0.z; a[3*132+rowL]=pa0.w;
        a[0*132+rowL+64]=pa1.x; a[1*132+rowL+64]=pa1.y; a[2*132+rowL+64]=pa1.z; a[3*132+rowL+64]=pa1.w;
    }
    CP_WAIT0();
    __syncthreads();

    for (int c = 0; c < 8; c++) {
        int cur = c & 1, nb = cur ^ 1;
        if (c + 1 < 8) {
            int k0 = (c + 1) * 16;
            pa0 = *(const float4*)(q_w + (long)idx_sh[rowL] * QD_ + k0 + kq);
            pa1 = *(const float4*)(q_w + (long)idx_sh[rowL + 64] * QD_ + k0 + kq);
            cp16(bs_base + nb * BS_BUF + bs_off, g_keyT + (k0 + bkk) * 64 + bcc);
            CP_COMMIT();
        }
#pragma unroll
        for (int kk = 0; kk < 16; kk++) {
            const float* ap = &sm.g.As[cur][kk][ty * 8];
            float4 a0 = *(const float4*)ap;
            float4 a1 = *(const float4*)(ap + 4);
            ulonglong2 bv = *(const ulonglong2*)&sm.g.Bs[cur][kk][tx * 4];
            ull ad[8] = {dup2(a0.x), dup2(a0.y), dup2(a0.z), dup2(a0.w),
                         dup2(a1.x), dup2(a1.y), dup2(a1.z), dup2(a1.w)};
#pragma unroll
            for (int i = 0; i < 8; i++) {
                fma2(acc[i][0], ad[i], bv.x);
                fma2(acc[i][1], ad[i], bv.y);
            }
        }
        if (c + 1 < 8) {
            float* a = &sm.g.As[nb][kq][0];
            a[0*132+rowL]=pa0.x; a[1*132+rowL]=pa0.y; a[2*132+rowL]=pa0.z; a[3*132+rowL]=pa0.w;
            a[0*132+rowL+64]=pa1.x; a[1*132+rowL+64]=pa1.y; a[2*132+rowL+64]=pa1.z; a[3*132+rowL+64]=pa1.w;
            CP_WAIT0();
        }
        __syncthreads();
    }

#pragma unroll
    for (int i = 0; i < 8; i++) {
        float v0, v1, v2, v3;
        unpack2(acc[i][0], v0, v1);
        unpack2(acc[i][1], v2, v3);
        float* lr = &sm.logits[ty * 8 + i][tx * 4];
        lr[0] = v0; lr[1] = v1; lr[2] = v2; lr[3] = v3;
    }
    __syncthreads();

    int wid = tid >> 5, lane = tid & 31;
    for (int rr = wid; rr < 128; rr += 8) {
        float v0 = sm.logits[rr][lane], v1 = sm.logits[rr][lane + 32];
        float mx = fmaxf(v0, v1);
#pragma unroll
        for (int o = 16; o; o >>= 1) mx = fmaxf(mx, __shfl_xor_sync(0xFFFFFFFFu, mx, o));
        float e0 = __expf(v0 - mx), e1 = __expf(v1 - mx);
        float s = e0 + e1;
#pragma unroll
        for (int o = 16; o; o >>= 1) s += __shfl_xor_sync(0xFFFFFFFFu, s, o);
        float inv = 1.f / s;
        g_w[(r0 + rr) * M_ + lane]      = e0 * inv;
        g_w[(r0 + rr) * M_ + 32 + lane] = e1 * inv;
    }
}

// ============================================================================
// K2: e/a GEMM
// ============================================================================
__global__ __launch_bounds__(256, 2) void ea_kernel(const int* __restrict__ qa_data,
                                                    const float* __restrict__ qa_w,
                                                    const float* __restrict__ eb,
                                                    const float* __restrict__ ab) {
    __shared__ __align__(16) float As[2][16][132];
    __shared__ __align__(16) float Bs[2][16][132];
    __shared__ int idx_sh[128];

    int tid = threadIdx.x;
    int r0  = blockIdx.x * 128;
    int half = blockIdx.y;
    const float* WT   = half ? g_awT : g_ewT;
    const float* bias = half ? ab : eb;
    if (tid < 128) idx_sh[tid] = qa_data[r0 + tid];
    __syncthreads();

    int tx = tid & 15, ty = tid >> 4;
    int rowL = tid >> 2;
    int kq   = (tid & 3) * 4;

    int ch0 = tid, ch1 = tid + 256;
    int bkk0 = ch0 >> 5, bcc0 = (ch0 & 31) * 4;
    int bkk1 = ch1 >> 5, bcc1 = (ch1 & 31) * 4;
    unsigned bs_base = (unsigned)__cvta_generic_to_shared(&Bs[0][0][0]);
    unsigned bo0 = (unsigned)((bkk0 * 132 + bcc0) * 4);
    unsigned bo1 = (unsigned)((bkk1 * 132 + bcc1) * 4);
    const unsigned BS_BUF = 16 * 132 * 4;

    ull acc[8][4];
#pragma unroll
    for (int i = 0; i < 8; i++)
#pragma unroll
        for (int j = 0; j < 4; j++) acc[i][j] = 0ull;

    float4 pa0, pa1;
    pa0 = *(const float4*)(qa_w + (long)idx_sh[rowL] * QAD_ + kq);
    pa1 = *(const float4*)(qa_w + (long)idx_sh[rowL + 64] * QAD_ + kq);
    cp16(bs_base + bo0, WT + bkk0 * 128 + bcc0);
    cp16(bs_base + bo1, WT + bkk1 * 128 + bcc1);
    CP_COMMIT();
    {
        float* a = &As[0][kq][0];
        a[0*132+rowL]=pa0.x; a[1*132+rowL]=pa0.y; a[2*132+rowL]=pa0.z; a[3*132+rowL]=pa0.w;
        a[0*132+rowL+64]=pa1.x; a[1*132+rowL+64]=pa1.y; a[2*132+rowL+64]=pa1.z; a[3*132+rowL+64]=pa1.w;
    }
    CP_WAIT0();
    __syncthreads();

    for (int c = 0; c < 16; c++) {
        int cur = c & 1, nb = cur ^ 1;
        if (c + 1 < 16) {
            int k0 = (c + 1) * 16;
            pa0 = *(const float4*)(qa_w + (long)idx_sh[rowL] * QAD_ + k0 + kq);
            pa1 = *(const float4*)(qa_w + (long)idx_sh[rowL + 64] * QAD_ + k0 + kq);
            cp16(bs_base + nb * BS_BUF + bo0, WT + (k0 + bkk0) * 128 + bcc0);
            cp16(bs_base + nb * BS_BUF + bo1, WT + (k0 + bkk1) * 128 + bcc1);
            CP_COMMIT();
        }
#pragma unroll
        for (int kk = 0; kk < 16; kk++) {
            const float* ap = &As[cur][kk][ty * 8];
            float4 a0 = *(const float4*)ap;
            float4 a1 = *(const float4*)(ap + 4);
            ulonglong2 b01 = *(const ulonglong2*)&Bs[cur][kk][tx * 8];
            ulonglong2 b23 = *(const ulonglong2*)(&Bs[cur][kk][tx * 8] + 4);
            ull ad[8] = {dup2(a0.x), dup2(a0.y), dup2(a0.z), dup2(a0.w),
                         dup2(a1.x), dup2(a1.y), dup2(a1.z), dup2(a1.w)};
#pragma unroll
            for (int i = 0; i < 8; i++) {
                fma2(acc[i][0], ad[i], b01.x);
                fma2(acc[i][1], ad[i], b01.y);
                fma2(acc[i][2], ad[i], b23.x);
                fma2(acc[i][3], ad[i], b23.y);
            }
        }
        if (c + 1 < 16) {
            float* a = &As[nb][kq][0];
            a[0*132+rowL]=pa0.x; a[1*132+rowL]=pa0.y; a[2*132+rowL]=pa0.z; a[3*132+rowL]=pa0.w;
            a[0*132+rowL+64]=pa1.x; a[1*132+rowL+64]=pa1.y; a[2*132+rowL+64]=pa1.z; a[3*132+rowL+64]=pa1.w;
            CP_WAIT0();
        }
        __syncthreads();
    }

    float* dst = half ? g_a : g_e;
#pragma unroll
    for (int i = 0; i < 8; i++) {
        int r = r0 + ty * 8 + i;
        float o[8];
        unpack2(acc[i][0], o[0], o[1]);
        unpack2(acc[i][1], o[2], o[3]);
        unpack2(acc[i][2], o[4], o[5]);
        unpack2(acc[i][3], o[6], o[7]);
        float res[8];
#pragma unroll
        for (int j = 0; j < 8; j++) {
            float x = o[j] + __ldg(bias + tx * 8 + j);
            res[j] = half ? tanhf(x) : (1.f / (1.f + __expf(-x)));
        }
        float4* dp = (float4*)(dst + (long)r * VD_ + tx * 8);
        dp[0] = make_float4(res[0], res[1], res[2], res[3]);
        dp[1] = make_float4(res[4], res[5], res[6], res[7]);
    }
}

// ============================================================================
// K3: sequential memory scan.  512 threads, software-pipelined:
//   compute(k) -> prefetch loads(k+1) -> shfl/store(k).
// ============================================================================
__global__ __launch_bounds__(512) void scan_kernel(const float* __restrict__ mem_value0) {
    extern __shared__ float smd[];
    float* w_all  = smd;                   // [256][64]
    float* ea_all = smd + S_ * 64;         // [256][128] interleaved {e,a}

    int bb = blockIdx.x >> 1, vh = blockIdx.x & 1;
    int tid = threadIdx.x;
    int rbase = bb * S_;

    // preload w (contiguous 64KB)
    const float4* wsrc = (const float4*)(g_w + (long)rbase * M_);
    float4* wdst = (float4*)w_all;
    for (int i = tid; i < S_ * M_ / 4; i += 512) wdst[i] = wsrc[i];
    // preload e,a interleaved: {e0,a0,e1,a1,...} per row
    for (int f = tid; f < S_ * 16; f += 512) {
        int t = f >> 4, c = (f & 15) * 4;
        float4 e4 = *(const float4*)(g_e + (long)(rbase + t) * VD_ + vh * 64 + c);
        float4 a4 = *(const float4*)(g_a + (long)(rbase + t) * VD_ + vh * 64 + c);
        float4 i0 = make_float4(e4.x, a4.x, e4.y, a4.y);
        float4 i1 = make_float4(e4.z, a4.z, e4.w, a4.w);
        *(float4*)&ea_all[t * 128 + c * 2]     = i0;
        *(float4*)&ea_all[t * 128 + c * 2 + 4] = i1;
    }

    int lane = tid & 31, wid = tid >> 5;
    int mh = lane & 7, vl = lane >> 3;
    int vloc = wid * 4 + vl;             // 0..63
    int v = vh * 64 + vloc;
    int mb = mh * 8;

    ull mm[4];
#pragma unroll
    for (int i = 0; i < 4; i++) {
        int m0 = mb + 2 * i;
        mm[i] = pack2(mem_value0[m0 * VD_ + v], mem_value0[(m0 + 1) * VD_ + v]);
    }
    __syncthreads();

    // register buffers for 4 steps
    ulonglong2 bwA[4], bwB[4];
    float2 bea[4];
#pragma unroll
    for (int u = 0; u < 4; u++) {
        bea[u] = *(const float2*)&ea_all[u * 128 + vloc * 2];
        bwA[u] = *(const ulonglong2*)&w_all[u * 64 + mb];
        bwB[u] = *(const ulonglong2*)&w_all[u * 64 + mb + 4];
    }

    for (int t0 = 0; t0 < S_; t0 += 4) {
        // 1. compute 4 steps from register buffers
        float rdv[4];
#pragma unroll
        for (int u = 0; u < 4; u++) {
            ull ne2 = dup2(-bea[u].x);
            ull a2v = dup2(bea[u].y);
            ull wv[4] = {bwA[u].x, bwA[u].y, bwB[u].x, bwB[u].y};
            ull rd2 = 0ull;
#pragma unroll
            for (int i = 0; i < 4; i++) {
                ull w2 = wv[i];
                ull tt = a2v; fma2(tt, ne2, mm[i]);   // a - e*mem
                fma2(rd2, w2, mm[i]);                 // read uses old mem
                fma2(mm[i], w2, tt);                  // mem += w*(a - e*mem)
            }
            float rl, rh; unpack2(rd2, rl, rh);
            rdv[u] = rl + rh;
        }
        // 2. prefetch next 4 steps (latency hides behind the shfl chain below)
        if (t0 + 4 < S_) {
            int tn = t0 + 4;
#pragma unroll
            for (int u = 0; u < 4; u++) {
                bea[u] = *(const float2*)&ea_all[(tn + u) * 128 + vloc * 2];
                bwA[u] = *(const ulonglong2*)&w_all[(tn + u) * 64 + mb];
                bwB[u] = *(const ulonglong2*)&w_all[(tn + u) * 64 + mb + 4];
            }
        }
        // 3. reduce + store
#pragma unroll
        for (int u = 0; u < 4; u++) rdv[u] += __shfl_xor_sync(0xFFFFFFFFu, rdv[u], 1);
#pragma unroll
        for (int u = 0; u < 4; u++) rdv[u] += __shfl_xor_sync(0xFFFFFFFFu, rdv[u], 2);
#pragma unroll
        for (int u = 0; u < 4; u++) rdv[u] += __shfl_xor_sync(0xFFFFFFFFu, rdv[u], 4);
        if (mh == 0) {
#pragma unroll
            for (int u = 0; u < 4; u++)
                g_reads[(long)(rbase + t0 + u) * VD_ + v] = rdv[u];
        }
    }
}

// ============================================================================
// K4: h = tanh([reads,q_emb] @ rwT + rb) fused with pred + BCE.
// ============================================================================
__global__ __launch_bounds__(256, 2) void read_pred_kernel(const int* __restrict__ q_data,
                                                           const float* __restrict__ q_w,
                                                           const float* __restrict__ rb,
                                                           const float* __restrict__ target,
                                                           const float* __restrict__ pw,
                                                           const float* __restrict__ pb,
                                                           float* __restrict__ out) {
    __shared__ __align__(16) float As[2][16][132];
    __shared__ __align__(16) float Bs[2][16][132];
    __shared__ int idx_sh[128];

    int tid = threadIdx.x;
    int r0  = blockIdx.x * 128;
    if (tid < 128) idx_sh[tid] = q_data[r0 + tid];
    __syncthreads();

    int tx = tid & 15, ty = tid >> 4;
    int rowL = tid >> 2;
    int kq   = (tid & 3) * 4;

    int ch0 = tid, ch1 = tid + 256;
    int bkk0 = ch0 >> 5, bcc0 = (ch0 & 31) * 4;
    int bkk1 = ch1 >> 5, bcc1 = (ch1 & 31) * 4;
    unsigned bs_base = (unsigned)__cvta_generic_to_shared(&Bs[0][0][0]);
    unsigned bo0 = (unsigned)((bkk0 * 132 + bcc0) * 4);
    unsigned bo1 = (unsigned)((bkk1 * 132 + bcc1) * 4);
    const unsigned BS_BUF = 16 * 132 * 4;

    ull acc[8][4];
#pragma unroll
    for (int i = 0; i < 8; i++)
#pragma unroll
        for (int j = 0; j < 4; j++) acc[i][j] = 0ull;

    float4 pa0, pa1;
    pa0 = *(const float4*)(g_reads + (long)(r0 + rowL) * VD_ + kq);
    pa1 = *(const float4*)(g_reads + (long)(r0 + rowL + 64) * VD_ + kq);
    cp16(bs_base + bo0, g_rwT + bkk0 * 128 + bcc0);
    cp16(bs_base + bo1, g_rwT + bkk1 * 128 + bcc1);
    CP_COMMIT();
    {
        float* a = &As[0][kq][0];
        a[0*132+rowL]=pa0.x; a[1*132+rowL]=pa0.y; a[2*132+rowL]=pa0.z; a[3*132+rowL]=pa0.w;
        a[0*132+rowL+64]=pa1.x; a[1*132+rowL+64]=pa1.y; a[2*132+rowL+64]=pa1.z; a[3*132+rowL+64]=pa1.w;
    }
    CP_WAIT0();
    __syncthreads();

    for (int c = 0; c < 16; c++) {
        int cur = c & 1, nb = cur ^ 1;
        if (c + 1 < 16) {
            int k0 = (c + 1) * 16;
            if (k0 < 128) {
                pa0 = *(const float4*)(g_reads + (long)(r0 + rowL) * VD_ + k0 + kq);
                pa1 = *(const float4*)(g_reads + (long)(r0 + rowL + 64) * VD_ + k0 + kq);
            } else {
                pa0 = *(const float4*)(q_w + (long)idx_sh[rowL] * QD_ + (k0 - 128) + kq);
                pa1 = *(const float4*)(q_w + (long)idx_sh[rowL + 64] * QD_ + (k0 - 128) + kq);
            }
            cp16(bs_base + nb * BS_BUF + bo0, g_rwT + (k0 + bkk0) * 128 + bcc0);
            cp16(bs_base + nb * BS_BUF + bo1, g_rwT + (k0 + bkk1) * 128 + bcc1);
            CP_COMMIT();
        }
#pragma unroll
        for (int kk = 0; kk < 16; kk++) {
            const float* ap = &As[cur][kk][ty * 8];
            float4 a0 = *(const float4*)ap;
            float4 a1 = *(const float4*)(ap + 4);
            ulonglong2 b01 = *(const ulonglong2*)&Bs[cur][kk][tx * 8];
            ulonglong2 b23 = *(const ulonglong2*)(&Bs[cur][kk][tx * 8] + 4);
            ull ad[8] = {dup2(a0.x), dup2(a0.y), dup2(a0.z), dup2(a0.w),
                         dup2(a1.x), dup2(a1.y), dup2(a1.z), dup2(a1.w)};
#pragma unroll
            for (int i = 0; i < 8; i++) {
                fma2(acc[i][0], ad[i], b01.x);
                fma2(acc[i][1], ad[i], b01.y);
                fma2(acc[i][2], ad[i], b23.x);
                fma2(acc[i][3], ad[i], b23.y);
            }
        }
        if (c + 1 < 16) {
            float* a = &As[nb][kq][0];
            a[0*132+rowL]=pa0.x; a[1*132+rowL]=pa0.y; a[2*132+rowL]=pa0.z; a[3*132+rowL]=pa0.w;
            a[0*132+rowL+64]=pa1.x; a[1*132+rowL+64]=pa1.y; a[2*132+rowL+64]=pa1.z; a[3*132+rowL+64]=pa1.w;
            CP_WAIT0();
        }
        __syncthreads();
    }

    float pbv = __ldg(pb);
    float s_bce = 0.f, s_m = 0.f;
#pragma unroll
    for (int i = 0; i < 8; i++) {
        int r = r0 + ty * 8 + i;
        float o[8];
        unpack2(acc[i][0], o[0], o[1]);
        unpack2(acc[i][1], o[2], o[3]);
        unpack2(acc[i][2], o[4], o[5]);
        unpack2(acc[i][3], o[6], o[7]);
        float part = 0.f;
#pragma unroll
        for (int j = 0; j < 8; j++) {
            int vv = tx * 8 + j;
            float hv = tanhf(o[j] + __ldg(rb + vv));
            part = fmaf(hv, __ldg(pw + vv), part);
        }
        part += __shfl_xor_sync(0xFFFFFFFFu, part, 1);
        part += __shfl_xor_sync(0xFFFFFFFFu, part, 2);
        part += __shfl_xor_sync(0xFFFFFFFFu, part, 4);
        part += __shfl_xor_sync(0xFFFFFFFFu, part, 8);
        if (tx == 0) {
            float logit = part + pbv;
            float pred = 1.f / (1.f + __expf(-logit));
            float tgt  = target[r];
            out[1 + r]      = pred;
            out[1 + BS + r] = tgt;
            float spa = log1pf(__expf(-fabsf(logit)));
            float sp_n = fmaxf(-logit, 0.f) + spa;
            float sp_p = fmaxf(logit, 0.f) + spa;
            float msk = (tgt >= 0.f) ? 1.f : 0.f;
            s_bce += (tgt * sp_n + (1.f - tgt) * sp_p) * msk;
            s_m   += msk;
        }
    }

    __shared__ float sb[8], smm[8];
#pragma unroll
    for (int o = 16; o; o >>= 1) {
        s_bce += __shfl_xor_sync(0xFFFFFFFFu, s_bce, o);
        s_m   += __shfl_xor_sync(0xFFFFFFFFu, s_m, o);
    }
    int lane = tid & 31, wid = tid >> 5;
    if (lane == 0) { sb[wid] = s_bce; smm[wid] = s_m; }
    __syncthreads();
    if (tid == 0) {
        float tb = 0.f, tm = 0.f;
#pragma unroll
        for (int i = 0; i < 8; i++) { tb += sb[i]; tm += smm[i]; }
        g_partial[2 * blockIdx.x]     = tb;
        g_partial[2 * blockIdx.x + 1] = tm;
    }
}

__global__ void loss_kernel(float* __restrict__ out) {
    if (threadIdx.x == 0) {
        float tb = 0.f, tm = 0.f;
        for (int i = 0; i < 128; i++) { tb += g_partial[2 * i]; tm += g_partial[2 * i + 1]; }
        out[0] = tb / fmaxf(tm, 1.f);
    }
}

// ============================================================================
extern "C" void kernel_launch(void* const* d_in, const int* in_sizes, int n_in,
                              void* d_out, int out_size) {
    const int*   q_data    = (const int*)d_in[0];
    const int*   qa_data   = (const int*)d_in[1];
    const float* target    = (const float*)d_in[2];
    const float* q_embed   = (const float*)d_in[3];
    const float* qa_embed  = (const float*)d_in[4];
    const float* mem_key   = (const float*)d_in[5];
    const float* mem_val0  = (const float*)d_in[6];
    const float* erase_w   = (const float*)d_in[7];
    const float* erase_b   = (const float*)d_in[8];
    const float* add_w     = (const float*)d_in[9];
    const float* add_b     = (const float*)d_in[10];
    const float* read_w    = (const float*)d_in[11];
    const float* read_b    = (const float*)d_in[12];
    const float* pred_w    = (const float*)d_in[13];
    const float* pred_b    = (const float*)d_in[14];
    float* out = (float*)d_out;

    cudaFuncSetAttribute(scan_kernel, cudaFuncAttributeMaxDynamicSharedMemorySize, 196608);

    transpose_kernel<<<dim3(128, 4), 256>>>(erase_w, add_w, read_w, mem_key);
    w_kernel        <<<BS / 128, 256>>>(q_data, q_embed);
    ea_kernel       <<<dim3(BS / 128, 2), 256>>>(qa_data, qa_embed, erase_b, add_b);
    scan_kernel     <<<B_ * 2, 512, 196608>>>(mem_val0);
    read_pred_kernel<<<BS / 128, 256>>>(q_data, q_embed, read_b, target, pred_w, pred_b, out);
    loss_kernel     <<<1, 32>>>(out);
}

// round 11
// speedup vs baseline: 1.0615x; 1.0615x over previous
#include <cuda_runtime.h>
#include <cuda_bf16.h>
#include <math.h>

#define B_    64
#define S_    256
#define BS    16384
#define M_    64
#define QD_   128
#define QAD_  256
#define VD_   128
#define FD_   128

typedef unsigned long long ull;

// ---------------- scratch ----------------
__device__ float g_w[BS * M_];
__device__ float g_e[BS * VD_];
__device__ float g_a[BS * VD_];
__device__ float g_reads[BS * VD_];
__device__ float g_partial[2 * 128];
__device__ float g_ewT[QAD_ * VD_];    // [256][128]
__device__ float g_awT[QAD_ * VD_];    // [256][128]
__device__ float g_rwT[256 * FD_];     // [256][128]
__device__ float g_keyT[QD_ * M_];     // [128][64]

// ---------------- helpers ----------------
__device__ __forceinline__ ull dup2(float x) {
    ull r; unsigned xi = __float_as_uint(x);
    asm("mov.b64 %0, {%1, %1};" : "=l"(r) : "r"(xi));
    return r;
}
__device__ __forceinline__ ull pack2(float lo, float hi) {
    ull r; unsigned a = __float_as_uint(lo), b = __float_as_uint(hi);
    asm("mov.b64 %0, {%1, %2};" : "=l"(r) : "r"(a), "r"(b));
    return r;
}
__device__ __forceinline__ void unpack2(ull v, float& lo, float& hi) {
    unsigned a, b;
    asm("mov.b64 {%0, %1}, %2;" : "=r"(a), "=r"(b) : "l"(v));
    lo = __uint_as_float(a); hi = __uint_as_float(b);
}
__device__ __forceinline__ void fma2(ull& d, ull a, ull b) {
    asm("fma.rn.f32x2 %0, %1, %2, %0;" : "+l"(d) : "l"(a), "l"(b));
}
__device__ __forceinline__ void cp16(unsigned s, const float* g) {
    asm volatile("cp.async.cg.shared.global [%0], [%1], 16;" :: "r"(s), "l"(g));
}
#define CP_COMMIT() asm volatile("cp.async.commit_group;")
#define CP_WAIT0()  asm volatile("cp.async.wait_group 0;" ::: "memory")

// ============================================================================
// K0: transpose weights into k-major scratch
// ============================================================================
__global__ void transpose_kernel(const float* __restrict__ ew,
                                 const float* __restrict__ aw,
                                 const float* __restrict__ rw,
                                 const float* __restrict__ key) {
    int t = blockIdx.x * 256 + threadIdx.x;
    int which = blockIdx.y;
    if (which < 3) {
        int k = t >> 7, n = t & 127;
        const float* src = which == 0 ? ew : (which == 1 ? aw : rw);
        float* dst = which == 0 ? g_ewT : (which == 1 ? g_awT : g_rwT);
        dst[k * 128 + n] = src[n * 256 + k];
    } else {
        if (t < QD_ * M_) {
            int k = t >> 6, n = t & 63;
            g_keyT[k * 64 + n] = key[n * 128 + k];
        }
    }
}

// ============================================================================
// K1: w = softmax(q_emb @ mem_key^T)
// ============================================================================
__global__ __launch_bounds__(256, 2) void w_kernel(const int* __restrict__ q_data,
                                                   const float* __restrict__ q_w) {
    __shared__ union {
        struct {
            __align__(16) float As[2][16][132];
            __align__(16) float Bs[2][16][68];
        } g;
        float logits[128][65];
    } sm;
    __shared__ int idx_sh[128];

    int tid = threadIdx.x;
    int r0  = blockIdx.x * 128;
    if (tid < 128) idx_sh[tid] = q_data[r0 + tid];
    __syncthreads();

    int tx = tid & 15, ty = tid >> 4;
    int rowL = tid >> 2;
    int kq   = (tid & 3) * 4;

    int bkk = tid >> 4, bcc = (tid & 15) * 4;
    unsigned bs_base = (unsigned)__cvta_generic_to_shared(&sm.g.Bs[0][0][0]);
    unsigned bs_off  = (unsigned)((bkk * 68 + bcc) * 4);
    const unsigned BS_BUF = 16 * 68 * 4;

    ull acc[8][2];
#pragma unroll
    for (int i = 0; i < 8; i++) { acc[i][0] = 0ull; acc[i][1] = 0ull; }

    float4 pa0, pa1;
    pa0 = *(const float4*)(q_w + (long)idx_sh[rowL] * QD_ + kq);
    pa1 = *(const float4*)(q_w + (long)idx_sh[rowL + 64] * QD_ + kq);
    cp16(bs_base + bs_off, g_keyT + bkk * 64 + bcc);
    CP_COMMIT();
    {
        float* a = &sm.g.As[0][kq][0];
        a[0*132+rowL]=pa0.x; a[1*132+rowL]=pa0.y; a[2*132+rowL]=pa0.z; a[3*132+rowL]=pa0.w;
        a[0*132+rowL+64]=pa1.x; a[1*132+rowL+64]=pa1.y; a[2*132+rowL+64]=pa1.z; a[3*132+rowL+64]=pa1.w;
    }
    CP_WAIT0();
    __syncthreads();

    for (int c = 0; c < 8; c++) {
        int cur = c & 1, nb = cur ^ 1;
        if (c + 1 < 8) {
            int k0 = (c + 1) * 16;
            pa0 = *(const float4*)(q_w + (long)idx_sh[rowL] * QD_ + k0 + kq);
            pa1 = *(const float4*)(q_w + (long)idx_sh[rowL + 64] * QD_ + k0 + kq);
            cp16(bs_base + nb * BS_BUF + bs_off, g_keyT + (k0 + bkk) * 64 + bcc);
            CP_COMMIT();
        }
#pragma unroll
        for (int kk = 0; kk < 16; kk++) {
            const float* ap = &sm.g.As[cur][kk][ty * 8];
            float4 a0 = *(const float4*)ap;
            float4 a1 = *(const float4*)(ap + 4);
            ulonglong2 bv = *(const ulonglong2*)&sm.g.Bs[cur][kk][tx * 4];
            ull ad[8] = {dup2(a0.x), dup2(a0.y), dup2(a0.z), dup2(a0.w),
                         dup2(a1.x), dup2(a1.y), dup2(a1.z), dup2(a1.w)};
#pragma unroll
            for (int i = 0; i < 8; i++) {
                fma2(acc[i][0], ad[i], bv.x);
                fma2(acc[i][1], ad[i], bv.y);
            }
        }
        if (c + 1 < 8) {
            float* a = &sm.g.As[nb][kq][0];
            a[0*132+rowL]=pa0.x; a[1*132+rowL]=pa0.y; a[2*132+rowL]=pa0.z; a[3*132+rowL]=pa0.w;
            a[0*132+rowL+64]=pa1.x; a[1*132+rowL+64]=pa1.y; a[2*132+rowL+64]=pa1.z; a[3*132+rowL+64]=pa1.w;
            CP_WAIT0();
        }
        __syncthreads();
    }

#pragma unroll
    for (int i = 0; i < 8; i++) {
        float v0, v1, v2, v3;
        unpack2(acc[i][0], v0, v1);
        unpack2(acc[i][1], v2, v3);
        float* lr = &sm.logits[ty * 8 + i][tx * 4];
        lr[0] = v0; lr[1] = v1; lr[2] = v2; lr[3] = v3;
    }
    __syncthreads();

    int wid = tid >> 5, lane = tid & 31;
    for (int rr = wid; rr < 128; rr += 8) {
        float v0 = sm.logits[rr][lane], v1 = sm.logits[rr][lane + 32];
        float mx = fmaxf(v0, v1);
#pragma unroll
        for (int o = 16; o; o >>= 1) mx = fmaxf(mx, __shfl_xor_sync(0xFFFFFFFFu, mx, o));
        float e0 = __expf(v0 - mx), e1 = __expf(v1 - mx);
        float s = e0 + e1;
#pragma unroll
        for (int o = 16; o; o >>= 1) s += __shfl_xor_sync(0xFFFFFFFFu, s, o);
        float inv = 1.f / s;
        g_w[(r0 + rr) * M_ + lane]      = e0 * inv;
        g_w[(r0 + rr) * M_ + 32 + lane] = e1 * inv;
    }
}

// ============================================================================
// K2: e/a GEMM
// ============================================================================
__global__ __launch_bounds__(256, 2) void ea_kernel(const int* __restrict__ qa_data,
                                                    const float* __restrict__ qa_w,
                                                    const float* __restrict__ eb,
                                                    const float* __restrict__ ab) {
    __shared__ __align__(16) float As[2][16][132];
    __shared__ __align__(16) float Bs[2][16][132];
    __shared__ int idx_sh[128];

    int tid = threadIdx.x;
    int r0  = blockIdx.x * 128;
    int half = blockIdx.y;
    const float* WT   = half ? g_awT : g_ewT;
    const float* bias = half ? ab : eb;
    if (tid < 128) idx_sh[tid] = qa_data[r0 + tid];
    __syncthreads();

    int tx = tid & 15, ty = tid >> 4;
    int rowL = tid >> 2;
    int kq   = (tid & 3) * 4;

    int ch0 = tid, ch1 = tid + 256;
    int bkk0 = ch0 >> 5, bcc0 = (ch0 & 31) * 4;
    int bkk1 = ch1 >> 5, bcc1 = (ch1 & 31) * 4;
    unsigned bs_base = (unsigned)__cvta_generic_to_shared(&Bs[0][0][0]);
    unsigned bo0 = (unsigned)((bkk0 * 132 + bcc0) * 4);
    unsigned bo1 = (unsigned)((bkk1 * 132 + bcc1) * 4);
    const unsigned BS_BUF = 16 * 132 * 4;

    ull acc[8][4];
#pragma unroll
    for (int i = 0; i < 8; i++)
#pragma unroll
        for (int j = 0; j < 4; j++) acc[i][j] = 0ull;

    float4 pa0, pa1;
    pa0 = *(const float4*)(qa_w + (long)idx_sh[rowL] * QAD_ + kq);
    pa1 = *(const float4*)(qa_w + (long)idx_sh[rowL + 64] * QAD_ + kq);
    cp16(bs_base + bo0, WT + bkk0 * 128 + bcc0);
    cp16(bs_base + bo1, WT + bkk1 * 128 + bcc1);
    CP_COMMIT();
    {
        float* a = &As[0][kq][0];
        a[0*132+rowL]=pa0.x; a[1*132+rowL]=pa0.y; a[2*132+rowL]=pa0.z; a[3*132+rowL]=pa0.w;
        a[0*132+rowL+64]=pa1.x; a[1*132+rowL+64]=pa1.y; a[2*132+rowL+64]=pa1.z; a[3*132+rowL+64]=pa1.w;
    }
    CP_WAIT0();
    __syncthreads();

    for (int c = 0; c < 16; c++) {
        int cur = c & 1, nb = cur ^ 1;
        if (c + 1 < 16) {
            int k0 = (c + 1) * 16;
            pa0 = *(const float4*)(qa_w + (long)idx_sh[rowL] * QAD_ + k0 + kq);
            pa1 = *(const float4*)(qa_w + (long)idx_sh[rowL + 64] * QAD_ + k0 + kq);
            cp16(bs_base + nb * BS_BUF + bo0, WT + (k0 + bkk0) * 128 + bcc0);
            cp16(bs_base + nb * BS_BUF + bo1, WT + (k0 + bkk1) * 128 + bcc1);
            CP_COMMIT();
        }
#pragma unroll
        for (int kk = 0; kk < 16; kk++) {
            const float* ap = &As[cur][kk][ty * 8];
            float4 a0 = *(const float4*)ap;
            float4 a1 = *(const float4*)(ap + 4);
            ulonglong2 b01 = *(const ulonglong2*)&Bs[cur][kk][tx * 8];
            ulonglong2 b23 = *(const ulonglong2*)(&Bs[cur][kk][tx * 8] + 4);
            ull ad[8] = {dup2(a0.x), dup2(a0.y), dup2(a0.z), dup2(a0.w),
                         dup2(a1.x), dup2(a1.y), dup2(a1.z), dup2(a1.w)};
#pragma unroll
            for (int i = 0; i < 8; i++) {
                fma2(acc[i][0], ad[i], b01.x);
                fma2(acc[i][1], ad[i], b01.y);
                fma2(acc[i][2], ad[i], b23.x);
                fma2(acc[i][3], ad[i], b23.y);
            }
        }
        if (c + 1 < 16) {
            float* a = &As[nb][kq][0];
            a[0*132+rowL]=pa0.x; a[1*132+rowL]=pa0.y; a[2*132+rowL]=pa0.z; a[3*132+rowL]=pa0.w;
            a[0*132+rowL+64]=pa1.x; a[1*132+rowL+64]=pa1.y; a[2*132+rowL+64]=pa1.z; a[3*132+rowL+64]=pa1.w;
            CP_WAIT0();
        }
        __syncthreads();
    }

    float* dst = half ? g_a : g_e;
#pragma unroll
    for (int i = 0; i < 8; i++) {
        int r = r0 + ty * 8 + i;
        float o[8];
        unpack2(acc[i][0], o[0], o[1]);
        unpack2(acc[i][1], o[2], o[3]);
        unpack2(acc[i][2], o[4], o[5]);
        unpack2(acc[i][3], o[6], o[7]);
        float res[8];
#pragma unroll
        for (int j = 0; j < 8; j++) {
            float x = o[j] + __ldg(bias + tx * 8 + j);
            res[j] = half ? tanhf(x) : (1.f / (1.f + __expf(-x)));
        }
        float4* dp = (float4*)(dst + (long)r * VD_ + tx * 8);
        dp[0] = make_float4(res[0], res[1], res[2], res[3]);
        dp[1] = make_float4(res[4], res[5], res[6], res[7]);
    }
}

// ============================================================================
// K3: sequential memory scan.  512 threads, unroll-8 + reduce-scatter:
//   per 8 steps per warp: 16 LDS.128 (w) + 4 LDS.128 (ea pairs)
//   + 7 SHFL + 1 STG  (half the MIO ops of the butterfly version).
// ============================================================================
__global__ __launch_bounds__(512) void scan_kernel(const float* __restrict__ mem_value0) {
    extern __shared__ float smd[];
    float* w_all  = smd;                   // [256][64]
    float* ea_all = smd + S_ * 64;         // [128][256]: (t/2)*256 + vloc*4 + (t&1)*2

    int bb = blockIdx.x >> 1, vh = blockIdx.x & 1;
    int tid = threadIdx.x;
    int rbase = bb * S_;

    // preload w (contiguous 64KB)
    const float4* wsrc = (const float4*)(g_w + (long)rbase * M_);
    float4* wdst = (float4*)w_all;
    for (int i = tid; i < S_ * M_ / 4; i += 512) wdst[i] = wsrc[i];
    // preload e,a packed 2 steps per 16B: ea[(t/2)*256 + vloc*4 + (t&1)*2 + {0,1}]
    for (int f = tid; f < S_ * 16; f += 512) {
        int t = f >> 4, c = (f & 15) * 4;
        float4 e4 = *(const float4*)(g_e + (long)(rbase + t) * VD_ + vh * 64 + c);
        float4 a4 = *(const float4*)(g_a + (long)(rbase + t) * VD_ + vh * 64 + c);
        float* base = &ea_all[(t >> 1) * 256 + (t & 1) * 2];
        *(float2*)&base[(c + 0) * 4] = make_float2(e4.x, a4.x);
        *(float2*)&base[(c + 1) * 4] = make_float2(e4.y, a4.y);
        *(float2*)&base[(c + 2) * 4] = make_float2(e4.z, a4.z);
        *(float2*)&base[(c + 3) * 4] = make_float2(e4.w, a4.w);
    }

    int lane = tid & 31, wid = tid >> 5;
    int mh = lane & 7, vl = lane >> 3;
    int vloc = wid * 4 + vl;             // 0..63
    int v = vh * 64 + vloc;
    int mb = mh * 8;

    ull mm[4];
#pragma unroll
    for (int i = 0; i < 4; i++) {
        int m0 = mb + 2 * i;
        mm[i] = pack2(mem_value0[m0 * VD_ + v], mem_value0[(m0 + 1) * VD_ + v]);
    }
    bool b4 = (mh & 4) != 0, b2 = (mh & 2) != 0, b1 = (mh & 1) != 0;
    __syncthreads();

    for (int t0 = 0; t0 < S_; t0 += 8) {
        // ea for 8 steps: 4 LDS.128 ({e_t,a_t,e_t+1,a_t+1})
        float4 eab[4];
#pragma unroll
        for (int j = 0; j < 4; j++)
            eab[j] = *(const float4*)&ea_all[((t0 >> 1) + j) * 256 + vloc * 4];

        float p[8];
#pragma unroll
        for (int u = 0; u < 8; u++) {
            float ec = (u & 1) ? eab[u >> 1].z : eab[u >> 1].x;
            float ac = (u & 1) ? eab[u >> 1].w : eab[u >> 1].y;
            ull ne2 = dup2(-ec);
            ull a2v = dup2(ac);
            int t = t0 + u;
            ulonglong2 wA = *(const ulonglong2*)&w_all[t * 64 + mb];
            ulonglong2 wB = *(const ulonglong2*)&w_all[t * 64 + mb + 4];
            ull wv[4] = {wA.x, wA.y, wB.x, wB.y};
            ull rd2 = 0ull;
#pragma unroll
            for (int i = 0; i < 4; i++) {
                ull w2 = wv[i];
                ull tt = a2v; fma2(tt, ne2, mm[i]);   // a - e*mem
                fma2(rd2, w2, mm[i]);                 // read uses old mem
                fma2(mm[i], w2, tt);                  // mem += w*(a - e*mem)
            }
            float rl, rh; unpack2(rd2, rl, rh);
            p[u] = rl + rh;
        }

        // reduce-scatter across the 8 mh-lanes: 7 shfls total.
        // After: this thread holds the full sum for step t0 + mh.
        float q4[4];
#pragma unroll
        for (int x = 0; x < 4; x++) {
            float send = b4 ? p[x] : p[x + 4];
            float recv = __shfl_xor_sync(0xFFFFFFFFu, send, 4);
            q4[x] = (b4 ? p[x + 4] : p[x]) + recv;
        }
        float q2[2];
#pragma unroll
        for (int x = 0; x < 2; x++) {
            float send = b2 ? q4[x] : q4[x + 2];
            float recv = __shfl_xor_sync(0xFFFFFFFFu, send, 2);
            q2[x] = (b2 ? q4[x + 2] : q4[x]) + recv;
        }
        {
            float send = b1 ? q2[0] : q2[1];
            float recv = __shfl_xor_sync(0xFFFFFFFFu, send, 1);
            float rd = (b1 ? q2[1] : q2[0]) + recv;
            g_reads[(long)(rbase + t0 + mh) * VD_ + v] = rd;
        }
    }
}

// ============================================================================
// K4: h = tanh([reads,q_emb] @ rwT + rb) fused with pred + BCE.
// ============================================================================
__global__ __launch_bounds__(256, 2) void read_pred_kernel(const int* __restrict__ q_data,
                                                           const float* __restrict__ q_w,
                                                           const float* __restrict__ rb,
                                                           const float* __restrict__ target,
                                                           const float* __restrict__ pw,
                                                           const float* __restrict__ pb,
                                                           float* __restrict__ out) {
    __shared__ __align__(16) float As[2][16][132];
    __shared__ __align__(16) float Bs[2][16][132];
    __shared__ int idx_sh[128];

    int tid = threadIdx.x;
    int r0  = blockIdx.x * 128;
    if (tid < 128) idx_sh[tid] = q_data[r0 + tid];
    __syncthreads();

    int tx = tid & 15, ty = tid >> 4;
    int rowL = tid >> 2;
    int kq   = (tid & 3) * 4;

    int ch0 = tid, ch1 = tid + 256;
    int bkk0 = ch0 >> 5, bcc0 = (ch0 & 31) * 4;
    int bkk1 = ch1 >> 5, bcc1 = (ch1 & 31) * 4;
    unsigned bs_base = (unsigned)__cvta_generic_to_shared(&Bs[0][0][0]);
    unsigned bo0 = (unsigned)((bkk0 * 132 + bcc0) * 4);
    unsigned bo1 = (unsigned)((bkk1 * 132 + bcc1) * 4);
    const unsigned BS_BUF = 16 * 132 * 4;

    ull acc[8][4];
#pragma unroll
    for (int i = 0; i < 8; i++)
#pragma unroll
        for (int j = 0; j < 4; j++) acc[i][j] = 0ull;

    float4 pa0, pa1;
    pa0 = *(const float4*)(g_reads + (long)(r0 + rowL) * VD_ + kq);
    pa1 = *(const float4*)(g_reads + (long)(r0 + rowL + 64) * VD_ + kq);
    cp16(bs_base + bo0, g_rwT + bkk0 * 128 + bcc0);
    cp16(bs_base + bo1, g_rwT + bkk1 * 128 + bcc1);
    CP_COMMIT();
    {
        float* a = &As[0][kq][0];
        a[0*132+rowL]=pa0.x; a[1*132+rowL]=pa0.y; a[2*132+rowL]=pa0.z; a[3*132+rowL]=pa0.w;
        a[0*132+rowL+64]=pa1.x; a[1*132+rowL+64]=pa1.y; a[2*132+rowL+64]=pa1.z; a[3*132+rowL+64]=pa1.w;
    }
    CP_WAIT0();
    __syncthreads();

    for (int c = 0; c < 16; c++) {
        int cur = c & 1, nb = cur ^ 1;
        if (c + 1 < 16) {
            int k0 = (c + 1) * 16;
            if (k0 < 128) {
                pa0 = *(const float4*)(g_reads + (long)(r0 + rowL) * VD_ + k0 + kq);
                pa1 = *(const float4*)(g_reads + (long)(r0 + rowL + 64) * VD_ + k0 + kq);
            } else {
                pa0 = *(const float4*)(q_w + (long)idx_sh[rowL] * QD_ + (k0 - 128) + kq);
                pa1 = *(const float4*)(q_w + (long)idx_sh[rowL + 64] * QD_ + (k0 - 128) + kq);
            }
            cp16(bs_base + nb * BS_BUF + bo0, g_rwT + (k0 + bkk0) * 128 + bcc0);
            cp16(bs_base + nb * BS_BUF + bo1, g_rwT + (k0 + bkk1) * 128 + bcc1);
            CP_COMMIT();
        }
#pragma unroll
        for (int kk = 0; kk < 16; kk++) {
            const float* ap = &As[cur][kk][ty * 8];
            float4 a0 = *(const float4*)ap;
            float4 a1 = *(const float4*)(ap + 4);
            ulonglong2 b01 = *(const ulonglong2*)&Bs[cur][kk][tx * 8];
            ulonglong2 b23 = *(const ulonglong2*)(&Bs[cur][kk][tx * 8] + 4);
            ull ad[8] = {dup2(a0.x), dup2(a0.y), dup2(a0.z), dup2(a0.w),
                         dup2(a1.x), dup2(a1.y), dup2(a1.z), dup2(a1.w)};
#pragma unroll
            for (int i = 0; i < 8; i++) {
                fma2(acc[i][0], ad[i], b01.x);
                fma2(acc[i][1], ad[i], b01.y);
                fma2(acc[i][2], ad[i], b23.x);
                fma2(acc[i][3], ad[i], b23.y);
            }
        }
        if (c + 1 < 16) {
            float* a = &As[nb][kq][0];
            a[0*132+rowL]=pa0.x; a[1*132+rowL]=pa0.y; a[2*132+rowL]=pa0.z; a[3*132+rowL]=pa0.w;
            a[0*132+rowL+64]=pa1.x; a[1*132+rowL+64]=pa1.y; a[2*132+rowL+64]=pa1.z; a[3*132+rowL+64]=pa1.w;
            CP_WAIT0();
        }
        __syncthreads();
    }

    float pbv = __ldg(pb);
    float s_bce = 0.f, s_m = 0.f;
#pragma unroll
    for (int i = 0; i < 8; i++) {
        int r = r0 + ty * 8 + i;
        float o[8];
        unpack2(acc[i][0], o[0], o[1]);
        unpack2(acc[i][1], o[2], o[3]);
        unpack2(acc[i][2], o[4], o[5]);
        unpack2(acc[i][3], o[6], o[7]);
        float part = 0.f;
#pragma unroll
        for (int j = 0; j < 8; j++) {
            int vv = tx * 8 + j;
            float hv = tanhf(o[j] + __ldg(rb + vv));
            part = fmaf(hv, __ldg(pw + vv), part);
        }
        part += __shfl_xor_sync(0xFFFFFFFFu, part, 1);
        part += __shfl_xor_sync(0xFFFFFFFFu, part, 2);
        part += __shfl_xor_sync(0xFFFFFFFFu, part, 4);
        part += __shfl_xor_sync(0xFFFFFFFFu, part, 8);
        if (tx == 0) {
            float logit = part + pbv;
            float pred = 1.f / (1.f + __expf(-logit));
            float tgt  = target[r];
            out[1 + r]      = pred;
            out[1 + BS + r] = tgt;
            float spa = log1pf(__expf(-fabsf(logit)));
            float sp_n = fmaxf(-logit, 0.f) + spa;
            float sp_p = fmaxf(logit, 0.f) + spa;
            float msk = (tgt >= 0.f) ? 1.f : 0.f;
            s_bce += (tgt * sp_n + (1.f - tgt) * sp_p) * msk;
            s_m   += msk;
        }
    }

    __shared__ float sb[8], smm[8];
#pragma unroll
    for (int o = 16; o; o >>= 1) {
        s_bce += __shfl_xor_sync(0xFFFFFFFFu, s_bce, o);
        s_m   += __shfl_xor_sync(0xFFFFFFFFu, s_m, o);
    }
    int lane = tid & 31, wid = tid >> 5;
    if (lane == 0) { sb[wid] = s_bce; smm[wid] = s_m; }
    __syncthreads();
    if (tid == 0) {
        float tb = 0.f, tm = 0.f;
#pragma unroll
        for (int i = 0; i < 8; i++) { tb += sb[i]; tm += smm[i]; }
        g_partial[2 * blockIdx.x]     = tb;
        g_partial[2 * blockIdx.x + 1] = tm;
    }
}

__global__ void loss_kernel(float* __restrict__ out) {
    if (threadIdx.x == 0) {
        float tb = 0.f, tm = 0.f;
        for (int i = 0; i < 128; i++) { tb += g_partial[2 * i]; tm += g_partial[2 * i + 1]; }
        out[0] = tb / fmaxf(tm, 1.f);
    }
}

// ============================================================================
extern "C" void kernel_launch(void* const* d_in, const int* in_sizes, int n_in,
                              void* d_out, int out_size) {
    const int*   q_data    = (const int*)d_in[0];
    const int*   qa_data   = (const int*)d_in[1];
    const float* target    = (const float*)d_in[2];
    const float* q_embed   = (const float*)d_in[3];
    const float* qa_embed  = (const float*)d_in[4];
    const float* mem_key   = (const float*)d_in[5];
    const float* mem_val0  = (const float*)d_in[6];
    const float* erase_w   = (const float*)d_in[7];
    const float* erase_b   = (const float*)d_in[8];
    const float* add_w     = (const float*)d_in[9];
    const float* add_b     = (const float*)d_in[10];
    const float* read_w    = (const float*)d_in[11];
    const float* read_b    = (const float*)d_in[12];
    const float* pred_w    = (const float*)d_in[13];
    const float* pred_b    = (const float*)d_in[14];
    float* out = (float*)d_out;

    cudaFuncSetAttribute(scan_kernel, cudaFuncAttributeMaxDynamicSharedMemorySize, 196608);

    transpose_kernel<<<dim3(128, 4), 256>>>(erase_w, add_w, read_w, mem_key);
    w_kernel        <<<BS / 128, 256>>>(q_data, q_embed);
    ea_kernel       <<<dim3(BS / 128, 2), 256>>>(qa_data, qa_embed, erase_b, add_b);
    scan_kernel     <<<B_ * 2, 512, 196608>>>(mem_val0);
    read_pred_kernel<<<BS / 128, 256>>>(q_data, q_embed, read_b, target, pred_w, pred_b, out);
    loss_kernel     <<<1, 32>>>(out);
}

// round 13
// speedup vs baseline: 1.1124x; 1.0479x over previous
#include <cuda_runtime.h>
#include <cuda_bf16.h>
#include <math.h>

#define B_    64
#define S_    256
#define BS    16384
#define M_    64
#define QD_   128
#define QAD_  256
#define VD_   128
#define FD_   128

typedef unsigned long long ull;

// ---------------- scratch ----------------
__device__ float g_w[BS * M_];
__device__ float g_e[BS * VD_];
__device__ float g_a[BS * VD_];
__device__ float g_reads[BS * VD_];
__device__ float g_partial[2 * 128];
__device__ float g_ewT[QAD_ * VD_];    // [256][128]
__device__ float g_awT[QAD_ * VD_];    // [256][128]
__device__ float g_rwT[256 * FD_];     // [256][128]
__device__ float g_keyT[QD_ * M_];     // [128][64]

// ---------------- helpers ----------------
__device__ __forceinline__ ull dup2(float x) {
    ull r; unsigned xi = __float_as_uint(x);
    asm("mov.b64 %0, {%1, %1};" : "=l"(r) : "r"(xi));
    return r;
}
__device__ __forceinline__ ull pack2(float lo, float hi) {
    ull r; unsigned a = __float_as_uint(lo), b = __float_as_uint(hi);
    asm("mov.b64 %0, {%1, %2};" : "=l"(r) : "r"(a), "r"(b));
    return r;
}
__device__ __forceinline__ void unpack2(ull v, float& lo, float& hi) {
    unsigned a, b;
    asm("mov.b64 {%0, %1}, %2;" : "=r"(a), "=r"(b) : "l"(v));
    lo = __uint_as_float(a); hi = __uint_as_float(b);
}
__device__ __forceinline__ void fma2(ull& d, ull a, ull b) {
    asm("fma.rn.f32x2 %0, %1, %2, %0;" : "+l"(d) : "l"(a), "l"(b));
}
__device__ __forceinline__ void cp16(unsigned s, const float* g) {
    asm volatile("cp.async.cg.shared.global [%0], [%1], 16;" :: "r"(s), "l"(g));
}
#define CP_COMMIT() asm volatile("cp.async.commit_group;")
#define CP_WAIT0()  asm volatile("cp.async.wait_group 0;" ::: "memory")

// ============================================================================
// K0: transpose weights into k-major scratch
// ============================================================================
__global__ void transpose_kernel(const float* __restrict__ ew,
                                 const float* __restrict__ aw,
                                 const float* __restrict__ rw,
                                 const float* __restrict__ key) {
    int t = blockIdx.x * 256 + threadIdx.x;
    int which = blockIdx.y;
    if (which < 3) {
        int k = t >> 7, n = t & 127;
        const float* src = which == 0 ? ew : (which == 1 ? aw : rw);
        float* dst = which == 0 ? g_ewT : (which == 1 ? g_awT : g_rwT);
        dst[k * 128 + n] = src[n * 256 + k];
    } else {
        if (t < QD_ * M_) {
            int k = t >> 6, n = t & 63;
            g_keyT[k * 64 + n] = key[n * 128 + k];
        }
    }
}

// ============================================================================
// K1: w = softmax(q_emb @ mem_key^T)
// ============================================================================
__global__ __launch_bounds__(256, 2) void w_kernel(const int* __restrict__ q_data,
                                                   const float* __restrict__ q_w) {
    __shared__ union {
        struct {
            __align__(16) float As[2][16][132];
            __align__(16) float Bs[2][16][68];
        } g;
        float logits[128][65];
    } sm;
    __shared__ int idx_sh[128];

    int tid = threadIdx.x;
    int r0  = blockIdx.x * 128;
    if (tid < 128) idx_sh[tid] = q_data[r0 + tid];
    __syncthreads();

    int tx = tid & 15, ty = tid >> 4;
    int rowL = tid >> 2;
    int kq   = (tid & 3) * 4;

    int bkk = tid >> 4, bcc = (tid & 15) * 4;
    unsigned bs_base = (unsigned)__cvta_generic_to_shared(&sm.g.Bs[0][0][0]);
    unsigned bs_off  = (unsigned)((bkk * 68 + bcc) * 4);
    const unsigned BS_BUF = 16 * 68 * 4;

    ull acc[8][2];
#pragma unroll
    for (int i = 0; i < 8; i++) { acc[i][0] = 0ull; acc[i][1] = 0ull; }

    float4 pa0, pa1;
    pa0 = *(const float4*)(q_w + (long)idx_sh[rowL] * QD_ + kq);
    pa1 = *(const float4*)(q_w + (long)idx_sh[rowL + 64] * QD_ + kq);
    cp16(bs_base + bs_off, g_keyT + bkk * 64 + bcc);
    CP_COMMIT();
    {
        float* a = &sm.g.As[0][kq][0];
        a[0*132+rowL]=pa0.x; a[1*132+rowL]=pa0.y; a[2*132+rowL]=pa0.z; a[3*132+rowL]=pa0.w;
        a[0*132+rowL+64]=pa1.x; a[1*132+rowL+64]=pa1.y; a[2*132+rowL+64]=pa1.z; a[3*132+rowL+64]=pa1.w;
    }
    CP_WAIT0();
    __syncthreads();

    for (int c = 0; c < 8; c++) {
        int cur = c & 1, nb = cur ^ 1;
        if (c + 1 < 8) {
            int k0 = (c + 1) * 16;
            pa0 = *(const float4*)(q_w + (long)idx_sh[rowL] * QD_ + k0 + kq);
            pa1 = *(const float4*)(q_w + (long)idx_sh[rowL + 64] * QD_ + k0 + kq);
            cp16(bs_base + nb * BS_BUF + bs_off, g_keyT + (k0 + bkk) * 64 + bcc);
            CP_COMMIT();
        }
#pragma unroll
        for (int kk = 0; kk < 16; kk++) {
            const float* ap = &sm.g.As[cur][kk][ty * 8];
            float4 a0 = *(const float4*)ap;
            float4 a1 = *(const float4*)(ap + 4);
            ulonglong2 bv = *(const ulonglong2*)&sm.g.Bs[cur][kk][tx * 4];
            ull ad[8] = {dup2(a0.x), dup2(a0.y), dup2(a0.z), dup2(a0.w),
                         dup2(a1.x), dup2(a1.y), dup2(a1.z), dup2(a1.w)};
#pragma unroll
            for (int i = 0; i < 8; i++) {
                fma2(acc[i][0], ad[i], bv.x);
                fma2(acc[i][1], ad[i], bv.y);
            }
        }
        if (c + 1 < 8) {
            float* a = &sm.g.As[nb][kq][0];
            a[0*132+rowL]=pa0.x; a[1*132+rowL]=pa0.y; a[2*132+rowL]=pa0.z; a[3*132+rowL]=pa0.w;
            a[0*132+rowL+64]=pa1.x; a[1*132+rowL+64]=pa1.y; a[2*132+rowL+64]=pa1.z; a[3*132+rowL+64]=pa1.w;
            CP_WAIT0();
        }
        __syncthreads();
    }

#pragma unroll
    for (int i = 0; i < 8; i++) {
        float v0, v1, v2, v3;
        unpack2(acc[i][0], v0, v1);
        unpack2(acc[i][1], v2, v3);
        float* lr = &sm.logits[ty * 8 + i][tx * 4];
        lr[0] = v0; lr[1] = v1; lr[2] = v2; lr[3] = v3;
    }
    __syncthreads();

    int wid = tid >> 5, lane = tid & 31;
    for (int rr = wid; rr < 128; rr += 8) {
        float v0 = sm.logits[rr][lane], v1 = sm.logits[rr][lane + 32];
        float mx = fmaxf(v0, v1);
#pragma unroll
        for (int o = 16; o; o >>= 1) mx = fmaxf(mx, __shfl_xor_sync(0xFFFFFFFFu, mx, o));
        float e0 = __expf(v0 - mx), e1 = __expf(v1 - mx);
        float s = e0 + e1;
#pragma unroll
        for (int o = 16; o; o >>= 1) s += __shfl_xor_sync(0xFFFFFFFFu, s, o);
        float inv = 1.f / s;
        g_w[(r0 + rr) * M_ + lane]      = e0 * inv;
        g_w[(r0 + rr) * M_ + 32 + lane] = e1 * inv;
    }
}

// ============================================================================
// K2: e/a GEMM
// ============================================================================
__global__ __launch_bounds__(256, 2) void ea_kernel(const int* __restrict__ qa_data,
                                                    const float* __restrict__ qa_w,
                                                    const float* __restrict__ eb,
                                                    const float* __restrict__ ab) {
    __shared__ __align__(16) float As[2][16][132];
    __shared__ __align__(16) float Bs[2][16][132];
    __shared__ int idx_sh[128];

    int tid = threadIdx.x;
    int r0  = blockIdx.x * 128;
    int half = blockIdx.y;
    const float* WT   = half ? g_awT : g_ewT;
    const float* bias = half ? ab : eb;
    if (tid < 128) idx_sh[tid] = qa_data[r0 + tid];
    __syncthreads();

    int tx = tid & 15, ty = tid >> 4;
    int rowL = tid >> 2;
    int kq   = (tid & 3) * 4;

    int ch0 = tid, ch1 = tid + 256;
    int bkk0 = ch0 >> 5, bcc0 = (ch0 & 31) * 4;
    int bkk1 = ch1 >> 5, bcc1 = (ch1 & 31) * 4;
    unsigned bs_base = (unsigned)__cvta_generic_to_shared(&Bs[0][0][0]);
    unsigned bo0 = (unsigned)((bkk0 * 132 + bcc0) * 4);
    unsigned bo1 = (unsigned)((bkk1 * 132 + bcc1) * 4);
    const unsigned BS_BUF = 16 * 132 * 4;

    ull acc[8][4];
#pragma unroll
    for (int i = 0; i < 8; i++)
#pragma unroll
        for (int j = 0; j < 4; j++) acc[i][j] = 0ull;

    float4 pa0, pa1;
    pa0 = *(const float4*)(qa_w + (long)idx_sh[rowL] * QAD_ + kq);
    pa1 = *(const float4*)(qa_w + (long)idx_sh[rowL + 64] * QAD_ + kq);
    cp16(bs_base + bo0, WT + bkk0 * 128 + bcc0);
    cp16(bs_base + bo1, WT + bkk1 * 128 + bcc1);
    CP_COMMIT();
    {
        float* a = &As[0][kq][0];
        a[0*132+rowL]=pa0.x; a[1*132+rowL]=pa0.y; a[2*132+rowL]=pa0.z; a[3*132+rowL]=pa0.w;
        a[0*132+rowL+64]=pa1.x; a[1*132+rowL+64]=pa1.y; a[2*132+rowL+64]=pa1.z; a[3*132+rowL+64]=pa1.w;
    }
    CP_WAIT0();
    __syncthreads();

    for (int c = 0; c < 16; c++) {
        int cur = c & 1, nb = cur ^ 1;
        if (c + 1 < 16) {
            int k0 = (c + 1) * 16;
            pa0 = *(const float4*)(qa_w + (long)idx_sh[rowL] * QAD_ + k0 + kq);
            pa1 = *(const float4*)(qa_w + (long)idx_sh[rowL + 64] * QAD_ + k0 + kq);
            cp16(bs_base + nb * BS_BUF + bo0, WT + (k0 + bkk0) * 128 + bcc0);
            cp16(bs_base + nb * BS_BUF + bo1, WT + (k0 + bkk1) * 128 + bcc1);
            CP_COMMIT();
        }
#pragma unroll
        for (int kk = 0; kk < 16; kk++) {
            const float* ap = &As[cur][kk][ty * 8];
            float4 a0 = *(const float4*)ap;
            float4 a1 = *(const float4*)(ap + 4);
            ulonglong2 b01 = *(const ulonglong2*)&Bs[cur][kk][tx * 8];
            ulonglong2 b23 = *(const ulonglong2*)(&Bs[cur][kk][tx * 8] + 4);
            ull ad[8] = {dup2(a0.x), dup2(a0.y), dup2(a0.z), dup2(a0.w),
                         dup2(a1.x), dup2(a1.y), dup2(a1.z), dup2(a1.w)};
#pragma unroll
            for (int i = 0; i < 8; i++) {
                fma2(acc[i][0], ad[i], b01.x);
                fma2(acc[i][1], ad[i], b01.y);
                fma2(acc[i][2], ad[i], b23.x);
                fma2(acc[i][3], ad[i], b23.y);
            }
        }
        if (c + 1 < 16) {
            float* a = &As[nb][kq][0];
            a[0*132+rowL]=pa0.x; a[1*132+rowL]=pa0.y; a[2*132+rowL]=pa0.z; a[3*132+rowL]=pa0.w;
            a[0*132+rowL+64]=pa1.x; a[1*132+rowL+64]=pa1.y; a[2*132+rowL+64]=pa1.z; a[3*132+rowL+64]=pa1.w;
            CP_WAIT0();
        }
        __syncthreads();
    }

    float* dst = half ? g_a : g_e;
#pragma unroll
    for (int i = 0; i < 8; i++) {
        int r = r0 + ty * 8 + i;
        float o[8];
        unpack2(acc[i][0], o[0], o[1]);
        unpack2(acc[i][1], o[2], o[3]);
        unpack2(acc[i][2], o[4], o[5]);
        unpack2(acc[i][3], o[6], o[7]);
        float res[8];
#pragma unroll
        for (int j = 0; j < 8; j++) {
            float x = o[j] + __ldg(bias + tx * 8 + j);
            res[j] = half ? tanhf(x) : (1.f / (1.f + __expf(-x)));
        }
        float4* dp = (float4*)(dst + (long)r * VD_ + tx * 8);
        dp[0] = make_float4(res[0], res[1], res[2], res[3]);
        dp[1] = make_float4(res[4], res[5], res[6], res[7]);
    }
}

// ============================================================================
// K3: sequential memory scan.  512 threads, grid = B_*4 (32 v-cols per block).
//   Lane map: 16 mh x 2 vl; thread owns 4 m-values (2 f32x2) for one v.
//   Per 16 steps per warp: 16 LDS.128 (w) + 8 LDS.128 (ea) + 15 SHFL + 1 STG.
//   Smem 128KB: w [256][64] + ea [128][128].
// ============================================================================
__global__ __launch_bounds__(512) void scan_kernel(const float* __restrict__ mem_value0) {
    extern __shared__ float smd[];
    float* w_all  = smd;                   // [256][64]  64KB
    float* ea_all = smd + S_ * 64;         // [128][128] 64KB: (t/2)*128 + vloc*4 + (t&1)*2

    int bb = blockIdx.x >> 2, vh = blockIdx.x & 3;   // vh: 32-col slice
    int tid = threadIdx.x;
    int rbase = bb * S_;

    // preload w (contiguous 64KB)
    const float4* wsrc = (const float4*)(g_w + (long)rbase * M_);
    float4* wdst = (float4*)w_all;
    for (int i = tid; i < S_ * M_ / 4; i += 512) wdst[i] = wsrc[i];
    // preload e,a packed 2 steps per 16B (32 cols)
    for (int f = tid; f < S_ * 8; f += 512) {
        int t = f >> 3, c = (f & 7) * 4;
        float4 e4 = *(const float4*)(g_e + (long)(rbase + t) * VD_ + vh * 32 + c);
        float4 a4 = *(const float4*)(g_a + (long)(rbase + t) * VD_ + vh * 32 + c);
        float* base = &ea_all[(t >> 1) * 128 + (t & 1) * 2];
        *(float2*)&base[(c + 0) * 4] = make_float2(e4.x, a4.x);
        *(float2*)&base[(c + 1) * 4] = make_float2(e4.y, a4.y);
        *(float2*)&base[(c + 2) * 4] = make_float2(e4.z, a4.z);
        *(float2*)&base[(c + 3) * 4] = make_float2(e4.w, a4.w);
    }

    int lane = tid & 31, wid = tid >> 5;           // wid 0..15
    int mh = lane & 15, vl = lane >> 4;            // mh 0..15, vl 0..1
    int vloc = wid * 2 + vl;                       // 0..31
    int v = vh * 32 + vloc;
    int mb = mh * 4;                               // 4 m-values per thread

    ull mm[2];
#pragma unroll
    for (int i = 0; i < 2; i++) {
        int m0 = mb + 2 * i;
        mm[i] = pack2(mem_value0[m0 * VD_ + v], mem_value0[(m0 + 1) * VD_ + v]);
    }
    bool b8 = (mh & 8) != 0, b4 = (mh & 4) != 0, b2 = (mh & 2) != 0, b1 = (mh & 1) != 0;
    __syncthreads();

    for (int t0 = 0; t0 < S_; t0 += 16) {
        float p[16];
#pragma unroll
        for (int j = 0; j < 8; j++) {
            // ea for steps t0+2j, t0+2j+1 : one LDS.128
            float4 eab = *(const float4*)&ea_all[((t0 >> 1) + j) * 128 + vloc * 4];
#pragma unroll
            for (int s = 0; s < 2; s++) {
                int u = 2 * j + s;
                float ec = s ? eab.z : eab.x;
                float ac = s ? eab.w : eab.y;
                ull ne2 = dup2(-ec);
                ull a2v = dup2(ac);
                ulonglong2 wA = *(const ulonglong2*)&w_all[(t0 + u) * 64 + mb];
                ull rd2 = 0ull;
#pragma unroll
                for (int i = 0; i < 2; i++) {
                    ull w2 = (i == 0) ? wA.x : wA.y;
                    ull tt = a2v; fma2(tt, ne2, mm[i]);   // a - e*mem
                    fma2(rd2, w2, mm[i]);                 // read uses old mem
                    fma2(mm[i], w2, tt);                  // mem += w*(a - e*mem)
                }
                float rl, rh; unpack2(rd2, rl, rh);
                p[u] = rl + rh;
            }
        }

        // reduce-scatter across 16 mh-lanes: 15 shfls; thread ends owning step t0+mh.
        float q8[8];
#pragma unroll
        for (int x = 0; x < 8; x++) {
            float send = b8 ? p[x] : p[x + 8];
            float recv = __shfl_xor_sync(0xFFFFFFFFu, send, 8);
            q8[x] = (b8 ? p[x + 8] : p[x]) + recv;
        }
        float q4[4];
#pragma unroll
        for (int x = 0; x < 4; x++) {
            float send = b4 ? q8[x] : q8[x + 4];
            float recv = __shfl_xor_sync(0xFFFFFFFFu, send, 4);
            q4[x] = (b4 ? q8[x + 4] : q8[x]) + recv;
        }
        float q2[2];
#pragma unroll
        for (int x = 0; x < 2; x++) {
            float send = b2 ? q4[x] : q4[x + 2];
            float recv = __shfl_xor_sync(0xFFFFFFFFu, send, 2);
            q2[x] = (b2 ? q4[x + 2] : q4[x]) + recv;
        }
        {
            float send = b1 ? q2[0] : q2[1];
            float recv = __shfl_xor_sync(0xFFFFFFFFu, send, 1);
            float rd = (b1 ? q2[1] : q2[0]) + recv;
            g_reads[(long)(rbase + t0 + mh) * VD_ + v] = rd;
        }
    }
}

// ============================================================================
// K4: h = tanh([reads,q_emb] @ rwT + rb) fused with pred + BCE.
// ============================================================================
__global__ __launch_bounds__(256, 2) void read_pred_kernel(const int* __restrict__ q_data,
                                                           const float* __restrict__ q_w,
                                                           const float* __restrict__ rb,
                                                           const float* __restrict__ target,
                                                           const float* __restrict__ pw,
                                                           const float* __restrict__ pb,
                                                           float* __restrict__ out) {
    __shared__ __align__(16) float As[2][16][132];
    __shared__ __align__(16) float Bs[2][16][132];
    __shared__ int idx_sh[128];

    int tid = threadIdx.x;
    int r0  = blockIdx.x * 128;
    if (tid < 128) idx_sh[tid] = q_data[r0 + tid];
    __syncthreads();

    int tx = tid & 15, ty = tid >> 4;
    int rowL = tid >> 2;
    int kq   = (tid & 3) * 4;

    int ch0 = tid, ch1 = tid + 256;
    int bkk0 = ch0 >> 5, bcc0 = (ch0 & 31) * 4;
    int bkk1 = ch1 >> 5, bcc1 = (ch1 & 31) * 4;
    unsigned bs_base = (unsigned)__cvta_generic_to_shared(&Bs[0][0][0]);
    unsigned bo0 = (unsigned)((bkk0 * 132 + bcc0) * 4);
    unsigned bo1 = (unsigned)((bkk1 * 132 + bcc1) * 4);
    const unsigned BS_BUF = 16 * 132 * 4;

    ull acc[8][4];
#pragma unroll
    for (int i = 0; i < 8; i++)
#pragma unroll
        for (int j = 0; j < 4; j++) acc[i][j] = 0ull;

    float4 pa0, pa1;
    pa0 = *(const float4*)(g_reads + (long)(r0 + rowL) * VD_ + kq);
    pa1 = *(const float4*)(g_reads + (long)(r0 + rowL + 64) * VD_ + kq);
    cp16(bs_base + bo0, g_rwT + bkk0 * 128 + bcc0);
    cp16(bs_base + bo1, g_rwT + bkk1 * 128 + bcc1);
    CP_COMMIT();
    {
        float* a = &As[0][kq][0];
        a[0*132+rowL]=pa0.x; a[1*132+rowL]=pa0.y; a[2*132+rowL]=pa0.z; a[3*132+rowL]=pa0.w;
        a[0*132+rowL+64]=pa1.x; a[1*132+rowL+64]=pa1.y; a[2*132+rowL+64]=pa1.z; a[3*132+rowL+64]=pa1.w;
    }
    CP_WAIT0();
    __syncthreads();

    for (int c = 0; c < 16; c++) {
        int cur = c & 1, nb = cur ^ 1;
        if (c + 1 < 16) {
            int k0 = (c + 1) * 16;
            if (k0 < 128) {
                pa0 = *(const float4*)(g_reads + (long)(r0 + rowL) * VD_ + k0 + kq);
                pa1 = *(const float4*)(g_reads + (long)(r0 + rowL + 64) * VD_ + k0 + kq);
            } else {
                pa0 = *(const float4*)(q_w + (long)idx_sh[rowL] * QD_ + (k0 - 128) + kq);
                pa1 = *(const float4*)(q_w + (long)idx_sh[rowL + 64] * QD_ + (k0 - 128) + kq);
            }
            cp16(bs_base + nb * BS_BUF + bo0, g_rwT + (k0 + bkk0) * 128 + bcc0);
            cp16(bs_base + nb * BS_BUF + bo1, g_rwT + (k0 + bkk1) * 128 + bcc1);
            CP_COMMIT();
        }
#pragma unroll
        for (int kk = 0; kk < 16; kk++) {
            const float* ap = &As[cur][kk][ty * 8];
            float4 a0 = *(const float4*)ap;
            float4 a1 = *(const float4*)(ap + 4);
            ulonglong2 b01 = *(const ulonglong2*)&Bs[cur][kk][tx * 8];
            ulonglong2 b23 = *(const ulonglong2*)(&Bs[cur][kk][tx * 8] + 4);
            ull ad[8] = {dup2(a0.x), dup2(a0.y), dup2(a0.z), dup2(a0.w),
                         dup2(a1.x), dup2(a1.y), dup2(a1.z), dup2(a1.w)};
#pragma unroll
            for (int i = 0; i < 8; i++) {
                fma2(acc[i][0], ad[i], b01.x);
                fma2(acc[i][1], ad[i], b01.y);
                fma2(acc[i][2], ad[i], b23.x);
                fma2(acc[i][3], ad[i], b23.y);
            }
        }
        if (c + 1 < 16) {
            float* a = &As[nb][kq][0];
            a[0*132+rowL]=pa0.x; a[1*132+rowL]=pa0.y; a[2*132+rowL]=pa0.z; a[3*132+rowL]=pa0.w;
            a[0*132+rowL+64]=pa1.x; a[1*132+rowL+64]=pa1.y; a[2*132+rowL+64]=pa1.z; a[3*132+rowL+64]=pa1.w;
            CP_WAIT0();
        }
        __syncthreads();
    }

    float pbv = __ldg(pb);
    float s_bce = 0.f, s_m = 0.f;
#pragma unroll
    for (int i = 0; i < 8; i++) {
        int r = r0 + ty * 8 + i;
        float o[8];
        unpack2(acc[i][0], o[0], o[1]);
        unpack2(acc[i][1], o[2], o[3]);
        unpack2(acc[i][2], o[4], o[5]);
        unpack2(acc[i][3], o[6], o[7]);
        float part = 0.f;
#pragma unroll
        for (int j = 0; j < 8; j++) {
            int vv = tx * 8 + j;
            float hv = tanhf(o[j] + __ldg(rb + vv));
            part = fmaf(hv, __ldg(pw + vv), part);
        }
        part += __shfl_xor_sync(0xFFFFFFFFu, part, 1);
        part += __shfl_xor_sync(0xFFFFFFFFu, part, 2);
        part += __shfl_xor_sync(0xFFFFFFFFu, part, 4);
        part += __shfl_xor_sync(0xFFFFFFFFu, part, 8);
        if (tx == 0) {
            float logit = part + pbv;
            float pred = 1.f / (1.f + __expf(-logit));
            float tgt  = target[r];
            out[1 + r]      = pred;
            out[1 + BS + r] = tgt;
            float spa = log1pf(__expf(-fabsf(logit)));
            float sp_n = fmaxf(-logit, 0.f) + spa;
            float sp_p = fmaxf(logit, 0.f) + spa;
            float msk = (tgt >= 0.f) ? 1.f : 0.f;
            s_bce += (tgt * sp_n + (1.f - tgt) * sp_p) * msk;
            s_m   += msk;
        }
    }

    __shared__ float sb[8], smm[8];
#pragma unroll
    for (int o = 16; o; o >>= 1) {
        s_bce += __shfl_xor_sync(0xFFFFFFFFu, s_bce, o);
        s_m   += __shfl_xor_sync(0xFFFFFFFFu, s_m, o);
    }
    int lane = tid & 31, wid = tid >> 5;
    if (lane == 0) { sb[wid] = s_bce; smm[wid] = s_m; }
    __syncthreads();
    if (tid == 0) {
        float tb = 0.f, tm = 0.f;
#pragma unroll
        for (int i = 0; i < 8; i++) { tb += sb[i]; tm += smm[i]; }
        g_partial[2 * blockIdx.x]     = tb;
        g_partial[2 * blockIdx.x + 1] = tm;
    }
}

__global__ void loss_kernel(float* __restrict__ out) {
    if (threadIdx.x == 0) {
        float tb = 0.f, tm = 0.f;
        for (int i = 0; i < 128; i++) { tb += g_partial[2 * i]; tm += g_partial[2 * i + 1]; }
        out[0] = tb / fmaxf(tm, 1.f);
    }
}

// ============================================================================
extern "C" void kernel_launch(void* const* d_in, const int* in_sizes, int n_in,
                              void* d_out, int out_size) {
    const int*   q_data    = (const int*)d_in[0];
    const int*   qa_data   = (const int*)d_in[1];
    const float* target    = (const float*)d_in[2];
    const float* q_embed   = (const float*)d_in[3];
    const float* qa_embed  = (const float*)d_in[4];
    const float* mem_key   = (const float*)d_in[5];
    const float* mem_val0  = (const float*)d_in[6];
    const float* erase_w   = (const float*)d_in[7];
    const float* erase_b   = (const float*)d_in[8];
    const float* add_w     = (const float*)d_in[9];
    const float* add_b     = (const float*)d_in[10];
    const float* read_w    = (const float*)d_in[11];
    const float* read_b    = (const float*)d_in[12];
    const float* pred_w    = (const float*)d_in[13];
    const float* pred_b    = (const float*)d_in[14];
    float* out = (float*)d_out;

    cudaFuncSetAttribute(scan_kernel, cudaFuncAttributeMaxDynamicSharedMemorySize, 131072);

    transpose_kernel<<<dim3(128, 4), 256>>>(erase_w, add_w, read_w, mem_key);
    w_kernel        <<<BS / 128, 256>>>(q_data, q_embed);
    ea_kernel       <<<dim3(BS / 128, 2), 256>>>(qa_data, qa_embed, erase_b, add_b);
    scan_kernel     <<<B_ * 4, 512, 131072>>>(mem_val0);
    read_pred_kernel<<<BS / 128, 256>>>(q_data, q_embed, read_b, target, pred_w, pred_b, out);
    loss_kernel     <<<1, 32>>>(out);
}